// round 9
// baseline (speedup 1.0000x reference)
#include <cuda_runtime.h>
#include <cstdint>

// SphConv, tf32 mma.sync. GEMM view: D[n=(b,k) grouped, m=o] with
//   A = weights (m16 rows = o, register-cached per lg and K-half),
//   B = x tile (k8 x n8 fragments via ldmatrix from XOR-swizzled smem).
// CTA = 2 batches -> 90 lg-grouped rows, overlapping n8 blocks, owner-predicated STG.

#define NCOEF 45
#define BSTRIDE (128 * NCOEF)

// A fragments: g_wpA[((wid*5 + lg)*16 + ks)*32 + lane] =
//   {W[o][i], W[o+8][i], W[o][i+4], W[o+8][i+4]} * scale_lg/128 (tf32-rounded),
//   o = wid*16 + (lane>>2), i = ks*8 + (lane&3).
__device__ float4 g_wpA[8 * 5 * 16 * 32];

__global__ void prep_w(const float* __restrict__ w) {
    int idx  = blockIdx.x * blockDim.x + threadIdx.x;   // 20480 exactly
    int lane = idx & 31;
    int ks   = (idx >> 5) & 15;
    int t    = idx >> 9;                  // 0..39
    int lg   = t % 5, wid = t / 5;
    int o    = wid * 16 + (lane >> 2);
    int i    = ks * 8 + (lane & 3);
    float l  = 2.0f * (float)lg;
    float s  = 6.28318530717958647692f *
               sqrtf(12.5663706143591729539f / (2.0f * l + 1.0f)) * (1.0f / 128.0f);
    float4 v;
    v.x = w[(o * 128 + i) * 5 + lg] * s;
    v.y = w[((o + 8) * 128 + i) * 5 + lg] * s;
    v.z = w[(o * 128 + i + 4) * 5 + lg] * s;
    v.w = w[((o + 8) * 128 + i + 4) * 5 + lg] * s;
    asm("cvt.rna.tf32.f32 %0, %0;" : "+f"(v.x));
    asm("cvt.rna.tf32.f32 %0, %0;" : "+f"(v.y));
    asm("cvt.rna.tf32.f32 %0, %0;" : "+f"(v.z));
    asm("cvt.rna.tf32.f32 %0, %0;" : "+f"(v.w));
    g_wpA[idx] = v;
}

__device__ __forceinline__ uint32_t smem_u32(const void* p) {
    uint32_t a;
    asm("{ .reg .u64 t; cvta.to.shared.u64 t, %1; cvt.u32.u64 %0, t; }" : "=r"(a) : "l"(p));
    return a;
}
__device__ __forceinline__ void ldsm4(uint32_t* r, uint32_t addr) {
    asm volatile("ldmatrix.sync.aligned.m8n8.x4.shared.b16 {%0,%1,%2,%3}, [%4];"
                 : "=r"(r[0]), "=r"(r[1]), "=r"(r[2]), "=r"(r[3]) : "r"(addr));
}
__device__ __forceinline__ void mma4(float* d, const uint32_t* a,
                                     uint32_t b0, uint32_t b1) {
    asm volatile(
        "mma.sync.aligned.m16n8k8.row.col.f32.tf32.tf32.f32 "
        "{%0,%1,%2,%3}, {%4,%5,%6,%7}, {%8,%9}, {%0,%1,%2,%3};"
        : "+f"(d[0]), "+f"(d[1]), "+f"(d[2]), "+f"(d[3])
        : "r"(a[0]), "r"(a[1]), "r"(a[2]), "r"(a[3]), "r"(b0), "r"(b1));
}

// One lg-run: L overlapping n8 blocks at BASES, K=128 in 2 halves of register-
// cached A, B via swizzled ldsm. Owner predicates give each row one writer.
template <int LG, int L, int B0, int B1, int B2, int B3, int B4>
__device__ __forceinline__ void do_run(uint32_t sbase, const float4* wpA,
                                       float* ob, int lane, int o0) {
    constexpr int BASES[5] = {B0, B1, B2, B3, B4};
    constexpr int GLO  = 2 * LG * LG - LG;
    constexpr int GLEN = 4 * LG + 1;
    constexpr int GLO2 = 2 * GLO;
    constexpr int GHI2 = GLO2 + 2 * GLEN;

    const int lr = lane >> 2, lc = lane & 3;
    const int lrow7 = lane & 7, lt = lane >> 3;

    float acc[L][4];
    #pragma unroll
    for (int j = 0; j < L; j++)
        #pragma unroll
        for (int e = 0; e < 4; e++) acc[j][e] = 0.0f;

    const float4* p = wpA + LG * 512;

    #pragma unroll
    for (int h = 0; h < 2; h++) {
        float4 a4[8];
        #pragma unroll
        for (int q = 0; q < 8; q++) a4[q] = p[(h * 8 + q) * 32];

        #pragma unroll
        for (int j = 0; j < L; j++) {
            const int row = BASES[j] + lrow7;
            const uint32_t rb = sbase + (uint32_t)(row * 512);
            const int sw = row & 7;
            #pragma unroll
            for (int ks2 = 0; ks2 < 4; ks2++) {
                const int g = h * 16 + ks2 * 4 + lt;
                uint32_t r[4];
                ldsm4(r, rb + (uint32_t)((g ^ sw) << 4));
                mma4(acc[j], (const uint32_t*)&a4[ks2 * 2],     r[0], r[1]);
                mma4(acc[j], (const uint32_t*)&a4[ks2 * 2 + 1], r[2], r[3]);
            }
        }
    }

    #pragma unroll
    for (int j = 0; j < L; j++) {
        const int wlo = (j == 0) ? GLO2 : BASES[j - 1] + 8;
        const int whi = (BASES[j] + 8 < GHI2) ? BASES[j] + 8 : GHI2;
        #pragma unroll
        for (int e = 0; e < 4; e++) {
            const int n = BASES[j] + 2 * lc + (e & 1);
            if (n >= wlo && n < whi) {
                const int local = n - GLO2;
                const int b_l = (local >= GLEN) ? 1 : 0;
                const int k = GLO + local - (b_l ? GLEN : 0);
                const int o = o0 + lr + ((e >> 1) << 3);
                ob[(size_t)b_l * BSTRIDE + o * NCOEF + k] = acc[j][e];
            }
        }
    }
}

__global__ void __launch_bounds__(256, 3)
sph_r9(const float* __restrict__ x, float* __restrict__ out) {
    __shared__ __align__(16) float Xs[90 * 128];   // 46080 B, XOR-swizzled rows
    const int tid = threadIdx.x;

    // ---- fill: batched LDG (MLP 16) -> cvt.rna -> swizzled grouped STS ----
    {
        const float* src = x + (size_t)blockIdx.x * 2 * BSTRIDE + tid;
        int k = tid % 45, i = tid / 45, b_l = 0;
        int t = 0;
        #pragma unroll
        for (int batch = 0; batch < 3; batch++) {
            const int nb = (batch < 2) ? 16 : 13;
            float v[16];
            #pragma unroll
            for (int u = 0; u < 16; u++)
                if (u < nb) v[u] = __ldg(src + (size_t)(t + u) * 256);
            #pragma unroll
            for (int u = 0; u < 16; u++) {
                if (u < nb) {
                    float val = v[u];
                    asm("cvt.rna.tf32.f32 %0, %0;" : "+f"(val));
                    const int lg = (k >= 28) ? 4 : (k >= 15) ? 3 : (k >= 6) ? 2
                                              : (k >= 1) ? 1 : 0;
                    const int glo = 2 * lg * lg - lg;
                    const int glen = 4 * lg + 1;
                    const int row = 2 * glo + b_l * glen + (k - glo);
                    Xs[row * 128 + ((((i >> 2) ^ (row & 7)) << 2) | (i & 3))] = val;
                    k += 31; i += 5;
                    if (k >= 45) { k -= 45; i += 1; }
                    if (i >= 128) { i -= 128; b_l = 1; }
                }
            }
            t += nb;
        }
    }
    __syncthreads();

    const int lane = tid & 31, wid = tid >> 5;
    const uint32_t sbase = smem_u32(Xs);
    const float4* wpA = g_wpA + (size_t)(wid * 5) * 512 + lane;
    float* ob = out + (size_t)blockIdx.x * 2 * BSTRIDE;
    const int o0 = wid * 16;

    do_run<0, 1, 0,  0,  0,  0,  0 >(sbase, wpA, ob, lane, o0);
    do_run<1, 2, 2,  4,  0,  0,  0 >(sbase, wpA, ob, lane, o0);
    do_run<2, 3, 12, 20, 22, 0,  0 >(sbase, wpA, ob, lane, o0);
    do_run<3, 4, 30, 38, 46, 48, 0 >(sbase, wpA, ob, lane, o0);
    do_run<4, 5, 56, 64, 72, 80, 82>(sbase, wpA, ob, lane, o0);
}

extern "C" void kernel_launch(void* const* d_in, const int* in_sizes, int n_in,
                              void* d_out, int out_size) {
    const float* x = (const float*)d_in[0];   // [16384, 128, 45] f32
    const float* w = (const float*)d_in[1];   // [128, 128, 5]   f32
    float* out = (float*)d_out;

    prep_w<<<80, 256>>>(w);
    sph_r9<<<8192, 256>>>(x, out);
}